// round 15
// baseline (speedup 1.0000x reference)
#include <cuda_runtime.h>
#include <cuda_fp16.h>
#include <mma.h>
#include <cstdint>

using namespace nvcuda;

#define BB 32
#define TT 512
#define DENC 512
#define HH 640
#define EE 640
#define JJ 640
#define VV 4096
#define G4 2560   // 4*H
#define KSPL 4

// ---------------- scratch ----------------
__device__ float d_gates_p[KSPL][BB][G4];
__device__ float d_h0[BB * HH];
__device__ float d_c0[BB * HH];
__device__ float d_h1[BB * HH];
__device__ float d_c1[BB * HH];
__device__ float d_gvec_p[2][BB][JJ];
__device__ __half d_fa[BB * TT * JJ];   // relu(f+g) fp16 (~21 MB)
__device__ __half d_wh[VV * JJ];        // wout fp16 (~5.2 MB)
__device__ __half d_ea[BB * TT * DENC]; // enc transposed fp16 (~16.8 MB)
__device__ __half d_we[JJ * DENC];      // wenc fp16 (~0.65 MB)

__device__ __forceinline__ float sigmoidf(float x) {
    return 1.0f / (1.0f + expf(-x));
}

// ---------------- cp.async helpers ----------------
__device__ __forceinline__ void cp16(uint32_t sdst, const void* gsrc) {
    asm volatile("cp.async.cg.shared.global [%0], [%1], 16;" :: "r"(sdst), "l"(gsrc));
}
__device__ __forceinline__ void cp_commit() {
    asm volatile("cp.async.commit_group;" ::: "memory");
}
__device__ __forceinline__ void cp_wait1() {
    asm volatile("cp.async.wait_group 1;" ::: "memory");
}

// ---------------- LSTM gates (layer0 reads embedding rows directly) ----------------
__global__ void __launch_bounds__(128) gates2_k(int layer, const int* __restrict__ targ,
                                                const float* __restrict__ embw,
                                                const float* __restrict__ hprev,
                                                const float* __restrict__ wih,
                                                const float* __restrict__ whh) {
    int tid = threadIdx.x;
    int j = blockIdx.x * 128 + tid;
    int kq = blockIdx.y;                  // 0..3
    int kbeg = kq * 320;                  // in combined 1280 space
    bool useX = (kbeg < EE);
    const float* w = useX ? wih : whh;
    int off = useX ? kbeg : kbeg - EE;

    __shared__ float xs[BB][320];
    for (int idx = tid; idx < BB * 80; idx += 128) {
        int b = idx / 80, c = idx % 80;
        const float* base;
        if (useX) {
            if (layer == 0) {
                int tok = targ[b];
                if (tok < 0 || tok >= VV) tok = 0;
                base = embw + (size_t)tok * EE;
            } else {
                base = d_h0 + (size_t)b * HH;
            }
        } else {
            base = hprev + (size_t)b * HH;
        }
        *(float4*)(&xs[b][c * 4]) = *(const float4*)(base + off + c * 4);
    }
    __syncthreads();

    float acc[BB];
#pragma unroll
    for (int b = 0; b < BB; b++) acc[b] = 0.f;

    const float4* wr = (const float4*)(w + (size_t)j * 640 + off);
    for (int kc = 0; kc < 80; kc++) {
        float4 wv = wr[kc];
#pragma unroll
        for (int b = 0; b < BB; b++) {
            float4 xv = *(const float4*)(&xs[b][kc * 4]);
            acc[b] = fmaf(wv.x, xv.x, fmaf(wv.y, xv.y, fmaf(wv.z, xv.z, fmaf(wv.w, xv.w, acc[b]))));
        }
    }
#pragma unroll
    for (int b = 0; b < BB; b++) d_gates_p[kq][b][j] = acc[b];
}

// ---------------- LSTM pointwise ----------------
__global__ void lstm_pw_k(int layer, const float* __restrict__ cprev,
                          const float* __restrict__ bih, const float* __restrict__ bhh) {
    int i = blockIdx.x * blockDim.x + threadIdx.x;  // B*H
    if (i >= BB * HH) return;
    int b = i / HH;
    int j = i % HH;
    float gv[4];
#pragma unroll
    for (int gidx = 0; gidx < 4; gidx++) {
        int jj = gidx * HH + j;
        float s = bih[jj] + bhh[jj];
#pragma unroll
        for (int q = 0; q < KSPL; q++) s += d_gates_p[q][b][jj];
        gv[gidx] = s;
    }
    float ig = sigmoidf(gv[0]);
    float fg = sigmoidf(gv[1]);
    float gg = tanhf(gv[2]);
    float og = sigmoidf(gv[3]);
    float c = fg * cprev[i] + ig * gg;
    float h = og * tanhf(c);
    if (layer == 0) { d_c0[i] = c; d_h0[i] = h; }
    else            { d_c1[i] = c; d_h1[i] = h; }
}

// ---------------- pred head ----------------
__global__ void __launch_bounds__(128) pred2_k(const float* __restrict__ wp) {
    int tid = threadIdx.x;
    int j = blockIdx.x * 128 + tid;
    int kq = blockIdx.y;
    int off = kq * 320;

    __shared__ float xs[BB][320];
    for (int idx = tid; idx < BB * 80; idx += 128) {
        int b = idx / 80, c = idx % 80;
        *(float4*)(&xs[b][c * 4]) = *(const float4*)(d_h1 + (size_t)b * HH + off + c * 4);
    }
    __syncthreads();

    float acc[BB];
#pragma unroll
    for (int b = 0; b < BB; b++) acc[b] = 0.f;
    const float4* wr = (const float4*)(wp + (size_t)j * HH + off);
    for (int kc = 0; kc < 80; kc++) {
        float4 wv = wr[kc];
#pragma unroll
        for (int b = 0; b < BB; b++) {
            float4 xv = *(const float4*)(&xs[b][kc * 4]);
            acc[b] = fmaf(wv.x, xv.x, fmaf(wv.y, xv.y, fmaf(wv.z, xv.z, fmaf(wv.w, xv.w, acc[b]))));
        }
    }
#pragma unroll
    for (int b = 0; b < BB; b++) d_gvec_p[kq][b][j] = acc[b];
}

// ---------------- combined weight convert: wout then wenc ----------------
#define N4_WH (VV * JJ / 4)
#define N4_WE (JJ * DENC / 4)
__global__ void wconv2_k(const float* __restrict__ wout, const float* __restrict__ wenc) {
    int i = blockIdx.x * blockDim.x + threadIdx.x;
    const float* src;
    __half* dst;
    int idx;
    if (i < N4_WH) { src = wout; dst = d_wh; idx = i; }
    else if (i < N4_WH + N4_WE) { src = wenc; dst = d_we; idx = i - N4_WH; }
    else return;
    float4 v = ((const float4*)src)[idx];
    __half2 h0 = __floats2half2_rn(v.x, v.y);
    __half2 h1 = __floats2half2_rn(v.z, v.w);
    uint2 u;
    u.x = *(uint32_t*)&h0;
    u.y = *(uint32_t*)&h1;
    *(uint2*)(&dst[(size_t)idx * 4]) = u;
}

// ---------------- enc transpose-convert ----------------
__global__ void __launch_bounds__(256) econv_k(const float* __restrict__ enc) {
    __shared__ float tile[32][33];
    int b = blockIdx.z;
    int k0 = blockIdx.y * 32;
    int t0 = blockIdx.x * 32;
    int tx = threadIdx.x & 31;
    int ty = threadIdx.x >> 5;    // 0..7
    const float* e = enc + (size_t)b * DENC * TT;
#pragma unroll
    for (int r = 0; r < 4; r++) {
        int kk = ty + r * 8;
        tile[kk][tx] = e[(size_t)(k0 + kk) * TT + t0 + tx];
    }
    __syncthreads();
#pragma unroll
    for (int r = 0; r < 4; r++) {
        int tt = ty + r * 8;
        d_ea[(size_t)(b * TT + t0 + tt) * DENC + k0 + tx] =
            __float2half_rn(tile[tx][tt]);
    }
}

// ================= pipelined wmma GEMM common (128x128, BK=64, 3-stage) =========
#define P_LDS 72
#define P_STAGE (128 * P_LDS * 2)       // 18432 bytes (one matrix, one stage)
#define NST 3
#define P_SMEM (NST * 2 * P_STAGE)      // 110592
#define STAG_LD 132

__device__ __forceinline__ void stage_load(uint32_t sbase, int stage,
                                           const __half* ga, size_t lda, int m0,
                                           const __half* gb, size_t ldb, int n0,
                                           int k0, int tid) {
    uint32_t abase = sbase + stage * 2 * P_STAGE;
    uint32_t bbase = abase + P_STAGE;
#pragma unroll
    for (int i = 0; i < 4; i++) {
        int e = i * 256 + tid;            // 0..1023
        int row = e >> 3;                 // 0..127
        int q = (e & 7) << 3;             // halves 0,8,...,56
        cp16(abase + (row * P_LDS + q) * 2, ga + (size_t)(m0 + row) * lda + k0 + q);
        cp16(bbase + (row * P_LDS + q) * 2, gb + (size_t)(n0 + row) * ldb + k0 + q);
    }
}

__device__ __forceinline__ void stage_mma(const __half* smem_gen, int stage,
                                          wmma::fragment<wmma::accumulator, 16, 16, 16, float> (&acc)[4][2],
                                          int wm, int wn) {
    const __half* As = smem_gen + stage * 2 * (128 * P_LDS);
    const __half* Bs = As + 128 * P_LDS;
#pragma unroll
    for (int ks = 0; ks < 4; ks++) {
        wmma::fragment<wmma::matrix_a, 16, 16, 16, __half, wmma::row_major> af[4];
        wmma::fragment<wmma::matrix_b, 16, 16, 16, __half, wmma::col_major> bf[2];
#pragma unroll
        for (int i = 0; i < 4; i++)
            wmma::load_matrix_sync(af[i], &As[(wm * 64 + i * 16) * P_LDS + ks * 16], P_LDS);
#pragma unroll
        for (int j = 0; j < 2; j++)
            wmma::load_matrix_sync(bf[j], &Bs[(wn * 32 + j * 16) * P_LDS + ks * 16], P_LDS);
#pragma unroll
        for (int i = 0; i < 4; i++)
#pragma unroll
            for (int j = 0; j < 2; j++)
                wmma::mma_sync(acc[i][j], af[i], bf[j], acc[i][j]);
    }
}

// ================= fgemm (wmma, 3-stage): writes relu(f + encb + g) fp16 ==========
__global__ void __launch_bounds__(256) fgemm_w_k(const float* __restrict__ encb,
                                                 const float* __restrict__ pbias) {
    extern __shared__ char dsm[];
    __half* sh = (__half*)dsm;
    float* stag = (float*)dsm;
    uint32_t sbase = (uint32_t)__cvta_generic_to_shared(dsm);

    int tid = threadIdx.x;
    int wid = tid >> 5;
    int wm = wid >> 2;
    int wn = wid & 3;
    int m0 = blockIdx.x * 128;
    int n0 = blockIdx.y * 128;
    int b = m0 / TT;

    wmma::fragment<wmma::accumulator, 16, 16, 16, float> acc[4][2];
#pragma unroll
    for (int i = 0; i < 4; i++)
#pragma unroll
        for (int j = 0; j < 2; j++) wmma::fill_fragment(acc[i][j], 0.f);

    const int NC = DENC / 64;   // 8
    stage_load(sbase, 0, d_ea, DENC, m0, d_we, DENC, n0, 0, tid);
    cp_commit();
    stage_load(sbase, 1, d_ea, DENC, m0, d_we, DENC, n0, 64, tid);
    cp_commit();
    for (int c = 0; c < NC; c++) {
        cp_wait1();                 // group c complete (c+1 may be in flight)
        __syncthreads();            // also protects stage (c+2)%3 from lagging compute
        if (c + 2 < NC)
            stage_load(sbase, (c + 2) % NST, d_ea, DENC, m0, d_we, DENC, n0, (c + 2) * 64, tid);
        cp_commit();                // empty groups keep wait_group counting valid
        stage_mma(sh, c % NST, acc, wm, wn);
    }
    __syncthreads();

#pragma unroll
    for (int p = 0; p < 2; p++) {
        if (wm == p) {
#pragma unroll
            for (int i = 0; i < 4; i++)
#pragma unroll
                for (int j = 0; j < 2; j++)
                    wmma::store_matrix_sync(&stag[(i * 16) * STAG_LD + wn * 32 + j * 16],
                                            acc[i][j], STAG_LD, wmma::mem_row_major);
        }
        __syncthreads();
        for (int t = tid; t < 64 * 32; t += 256) {
            int rr = t >> 5;
            int c4 = (t & 31) << 2;
            float4 v = *(float4*)(&stag[rr * STAG_LD + c4]);
            float4 eb = *(const float4*)(encb + n0 + c4);
            float4 g0 = *(const float4*)(&d_gvec_p[0][b][n0 + c4]);
            float4 g1 = *(const float4*)(&d_gvec_p[1][b][n0 + c4]);
            float4 pb = *(const float4*)(pbias + n0 + c4);
            float v0 = fmaxf(v.x + eb.x + g0.x + g1.x + pb.x, 0.f);
            float v1 = fmaxf(v.y + eb.y + g0.y + g1.y + pb.y, 0.f);
            float v2 = fmaxf(v.z + eb.z + g0.z + g1.z + pb.z, 0.f);
            float v3 = fmaxf(v.w + eb.w + g0.w + g1.w + pb.w, 0.f);
            __half2 h0 = __floats2half2_rn(v0, v1);
            __half2 h1 = __floats2half2_rn(v2, v3);
            uint2 u;
            u.x = *(uint32_t*)&h0;
            u.y = *(uint32_t*)&h1;
            *(uint2*)(&d_fa[(size_t)(m0 + p * 64 + rr) * JJ + n0 + c4]) = u;
        }
        __syncthreads();
    }
}

// ================= out GEMM (wmma, 3-stage, 128x128) ============
__global__ void __launch_bounds__(256) outgemm_w_k(const float* __restrict__ outb,
                                                   float* __restrict__ out,
                                                   long long out_elems) {
    extern __shared__ char dsm[];
    __half* sh = (__half*)dsm;
    float* stag = (float*)dsm;
    uint32_t sbase = (uint32_t)__cvta_generic_to_shared(dsm);

    int tid = threadIdx.x;
    int wid = tid >> 5;
    int wm = wid >> 2;
    int wn = wid & 3;
    int m0 = blockIdx.x * 128;
    int n0 = blockIdx.y * 128;

    wmma::fragment<wmma::accumulator, 16, 16, 16, float> acc[4][2];
#pragma unroll
    for (int i = 0; i < 4; i++)
#pragma unroll
        for (int j = 0; j < 2; j++) wmma::fill_fragment(acc[i][j], 0.f);

    const int NC = JJ / 64;   // 10
    stage_load(sbase, 0, d_fa, JJ, m0, d_wh, JJ, n0, 0, tid);
    cp_commit();
    stage_load(sbase, 1, d_fa, JJ, m0, d_wh, JJ, n0, 64, tid);
    cp_commit();
    for (int c = 0; c < NC; c++) {
        cp_wait1();
        __syncthreads();
        if (c + 2 < NC)
            stage_load(sbase, (c + 2) % NST, d_fa, JJ, m0, d_wh, JJ, n0, (c + 2) * 64, tid);
        cp_commit();
        stage_mma(sh, c % NST, acc, wm, wn);
    }
    __syncthreads();

#pragma unroll
    for (int p = 0; p < 2; p++) {
        if (wm == p) {
#pragma unroll
            for (int i = 0; i < 4; i++)
#pragma unroll
                for (int j = 0; j < 2; j++)
                    wmma::store_matrix_sync(&stag[(i * 16) * STAG_LD + wn * 32 + j * 16],
                                            acc[i][j], STAG_LD, wmma::mem_row_major);
        }
        __syncthreads();
        for (int t = tid; t < 64 * 32; t += 256) {
            int rr = t >> 5;
            int c4 = (t & 31) << 2;
            float4 v = *(float4*)(&stag[rr * STAG_LD + c4]);
            float4 bias = *(const float4*)(outb + n0 + c4);
            long long idx = (long long)(m0 + p * 64 + rr) * VV + n0 + c4;
            if (idx + 3 < out_elems) {
                float4 o;
                o.x = v.x + bias.x;
                o.y = v.y + bias.y;
                o.z = v.z + bias.z;
                o.w = v.w + bias.w;
                *(float4*)(&out[idx]) = o;
            }
        }
        __syncthreads();
    }
}

// ---------------- tail ----------------
__global__ void tail_k(const int* __restrict__ tlen, float* __restrict__ out,
                       long long out_elems) {
    int i = blockIdx.x * blockDim.x + threadIdx.x;
    long long base = (long long)BB * TT * VV;
    if (i < BB) {
        long long idx = base + i;
        if (idx < out_elems) out[idx] = (float)tlen[i];
    }
    if (i < 2 * BB * HH) {
        float h = (i < BB * HH) ? d_h0[i] : d_h1[i - BB * HH];
        float c = (i < BB * HH) ? d_c0[i] : d_c1[i - BB * HH];
        long long ih = base + BB + i;
        long long ic = base + BB + 2LL * BB * HH + i;
        if (ih < out_elems) out[ih] = h;
        if (ic < out_elems) out[ic] = c;
    }
}

extern "C" void kernel_launch(void* const* d_in, const int* in_sizes, int n_in,
                              void* d_out, int out_size) {
    const float* enc       = (const float*)d_in[0];
    const int* targ        = (const int*)d_in[1];
    const int* tlen        = (const int*)d_in[2];
    const float* st1       = (const float*)d_in[3];
    const float* st2       = (const float*)d_in[4];
    const float* wih0      = (const float*)d_in[5];
    const float* whh0      = (const float*)d_in[6];
    const float* bih0      = (const float*)d_in[7];
    const float* bhh0      = (const float*)d_in[8];
    const float* wih1      = (const float*)d_in[9];
    const float* whh1      = (const float*)d_in[10];
    const float* bih1      = (const float*)d_in[11];
    const float* bhh1      = (const float*)d_in[12];
    const float* embw      = (const float*)d_in[13];
    const float* wenc      = (const float*)d_in[14];
    const float* encb      = (const float*)d_in[15];
    const float* wpred     = (const float*)d_in[16];
    const float* pbias     = (const float*)d_in[17];
    const float* wout      = (const float*)d_in[18];
    const float* outb      = (const float*)d_in[19];
    float* out = (float*)d_out;
    long long out_elems = (long long)out_size;

    cudaFuncSetAttribute(fgemm_w_k, cudaFuncAttributeMaxDynamicSharedMemorySize, P_SMEM);
    cudaFuncSetAttribute(outgemm_w_k, cudaFuncAttributeMaxDynamicSharedMemorySize, P_SMEM);

    wconv2_k<<<(N4_WH + N4_WE + 255) / 256, 256>>>(wout, wenc);
    econv_k<<<dim3(TT / 32, DENC / 32, BB), 256>>>(enc);

    gates2_k<<<dim3(G4 / 128, KSPL), 128>>>(0, targ, embw, st1, wih0, whh0);
    lstm_pw_k<<<(BB * HH + 255) / 256, 256>>>(0, st2, bih0, bhh0);

    gates2_k<<<dim3(G4 / 128, KSPL), 128>>>(1, targ, embw, st1 + (size_t)BB * HH, wih1, whh1);
    lstm_pw_k<<<(BB * HH + 255) / 256, 256>>>(1, st2 + (size_t)BB * HH, bih1, bhh1);

    pred2_k<<<dim3(JJ / 128, 2), 128>>>(wpred);

    fgemm_w_k<<<dim3(BB * TT / 128, JJ / 128), 256, P_SMEM>>>(encb, pbias);

    outgemm_w_k<<<dim3(BB * TT / 128, VV / 128), 256, P_SMEM>>>(outb, out, out_elems);

    tail_k<<<(2 * BB * HH + 255) / 256, 256>>>(tlen, out, out_elems);
}

// round 17
// speedup vs baseline: 1.1207x; 1.1207x over previous
#include <cuda_runtime.h>
#include <cuda_fp16.h>
#include <mma.h>
#include <cstdint>

using namespace nvcuda;

#define BB 32
#define TT 512
#define DENC 512
#define HH 640
#define EE 640
#define JJ 640
#define VV 4096
#define G4 2560   // 4*H
#define KSPL 8
#define PSPL 4

// ---------------- scratch ----------------
__device__ float d_gates_p[KSPL][BB][G4];
__device__ float d_h0[BB * HH];
__device__ float d_c0[BB * HH];
__device__ float d_h1[BB * HH];
__device__ float d_c1[BB * HH];
__device__ float d_gvec_p[PSPL][BB][JJ];
__device__ __half d_fa[BB * TT * JJ];   // relu(f+g) fp16 (~21 MB)
__device__ __half d_wh[VV * JJ];        // wout fp16 (~5.2 MB)
__device__ __half d_ea[BB * TT * DENC]; // enc transposed fp16 (~16.8 MB)
__device__ __half d_we[JJ * DENC];      // wenc fp16 (~0.65 MB)

__device__ __forceinline__ float sigmoidf(float x) {
    return 1.0f / (1.0f + expf(-x));
}

// ---------------- cp.async helpers ----------------
__device__ __forceinline__ void cp16(uint32_t sdst, const void* gsrc) {
    asm volatile("cp.async.cg.shared.global [%0], [%1], 16;" :: "r"(sdst), "l"(gsrc));
}
__device__ __forceinline__ void cp_commit() {
    asm volatile("cp.async.commit_group;" ::: "memory");
}
__device__ __forceinline__ void cp_wait0() {
    asm volatile("cp.async.wait_group 0;" ::: "memory");
}

// ---------------- LSTM gates (k-split 8, layer0 reads embedding rows directly) -----
__global__ void __launch_bounds__(128) gates2_k(int layer, const int* __restrict__ targ,
                                                const float* __restrict__ embw,
                                                const float* __restrict__ hprev,
                                                const float* __restrict__ wih,
                                                const float* __restrict__ whh) {
    int tid = threadIdx.x;
    int j = blockIdx.x * 128 + tid;
    int kq = blockIdx.y;                  // 0..7
    int kbeg = kq * 160;                  // in combined 1280 space
    bool useX = (kbeg < EE);
    const float* w = useX ? wih : whh;
    int off = useX ? kbeg : kbeg - EE;

    __shared__ float xs[BB][160];
    for (int idx = tid; idx < BB * 40; idx += 128) {   // 40 float4 per row
        int b = idx / 40, c = idx % 40;
        const float* base;
        if (useX) {
            if (layer == 0) {
                int tok = targ[b];
                if (tok < 0 || tok >= VV) tok = 0;
                base = embw + (size_t)tok * EE;
            } else {
                base = d_h0 + (size_t)b * HH;
            }
        } else {
            base = hprev + (size_t)b * HH;
        }
        *(float4*)(&xs[b][c * 4]) = *(const float4*)(base + off + c * 4);
    }
    __syncthreads();

    float acc[BB];
#pragma unroll
    for (int b = 0; b < BB; b++) acc[b] = 0.f;

    const float4* wr = (const float4*)(w + (size_t)j * 640 + off);
    for (int kc = 0; kc < 40; kc++) {
        float4 wv = wr[kc];
#pragma unroll
        for (int b = 0; b < BB; b++) {
            float4 xv = *(const float4*)(&xs[b][kc * 4]);
            acc[b] = fmaf(wv.x, xv.x, fmaf(wv.y, xv.y, fmaf(wv.z, xv.z, fmaf(wv.w, xv.w, acc[b]))));
        }
    }
#pragma unroll
    for (int b = 0; b < BB; b++) d_gates_p[kq][b][j] = acc[b];
}

// ---------------- LSTM pointwise ----------------
__global__ void lstm_pw_k(int layer, const float* __restrict__ cprev,
                          const float* __restrict__ bih, const float* __restrict__ bhh) {
    int i = blockIdx.x * blockDim.x + threadIdx.x;  // B*H
    if (i >= BB * HH) return;
    int b = i / HH;
    int j = i % HH;
    float gv[4];
#pragma unroll
    for (int gidx = 0; gidx < 4; gidx++) {
        int jj = gidx * HH + j;
        float s = bih[jj] + bhh[jj];
#pragma unroll
        for (int q = 0; q < KSPL; q++) s += d_gates_p[q][b][jj];
        gv[gidx] = s;
    }
    float ig = sigmoidf(gv[0]);
    float fg = sigmoidf(gv[1]);
    float gg = tanhf(gv[2]);
    float og = sigmoidf(gv[3]);
    float c = fg * cprev[i] + ig * gg;
    float h = og * tanhf(c);
    if (layer == 0) { d_c0[i] = c; d_h0[i] = h; }
    else            { d_c1[i] = c; d_h1[i] = h; }
}

// ---------------- pred head (k-split 4) ----------------
__global__ void __launch_bounds__(128) pred2_k(const float* __restrict__ wp) {
    int tid = threadIdx.x;
    int j = blockIdx.x * 128 + tid;
    int kq = blockIdx.y;             // 0..3
    int off = kq * 160;

    __shared__ float xs[BB][160];
    for (int idx = tid; idx < BB * 40; idx += 128) {
        int b = idx / 40, c = idx % 40;
        *(float4*)(&xs[b][c * 4]) = *(const float4*)(d_h1 + (size_t)b * HH + off + c * 4);
    }
    __syncthreads();

    float acc[BB];
#pragma unroll
    for (int b = 0; b < BB; b++) acc[b] = 0.f;
    const float4* wr = (const float4*)(wp + (size_t)j * HH + off);
    for (int kc = 0; kc < 40; kc++) {
        float4 wv = wr[kc];
#pragma unroll
        for (int b = 0; b < BB; b++) {
            float4 xv = *(const float4*)(&xs[b][kc * 4]);
            acc[b] = fmaf(wv.x, xv.x, fmaf(wv.y, xv.y, fmaf(wv.z, xv.z, fmaf(wv.w, xv.w, acc[b]))));
        }
    }
#pragma unroll
    for (int b = 0; b < BB; b++) d_gvec_p[kq][b][j] = acc[b];
}

// ---------------- combined weight convert: wout then wenc ----------------
#define N4_WH (VV * JJ / 4)
#define N4_WE (JJ * DENC / 4)
__global__ void wconv2_k(const float* __restrict__ wout, const float* __restrict__ wenc) {
    int i = blockIdx.x * blockDim.x + threadIdx.x;
    const float* src;
    __half* dst;
    int idx;
    if (i < N4_WH) { src = wout; dst = d_wh; idx = i; }
    else if (i < N4_WH + N4_WE) { src = wenc; dst = d_we; idx = i - N4_WH; }
    else return;
    float4 v = ((const float4*)src)[idx];
    __half2 h0 = __floats2half2_rn(v.x, v.y);
    __half2 h1 = __floats2half2_rn(v.z, v.w);
    uint2 u;
    u.x = *(uint32_t*)&h0;
    u.y = *(uint32_t*)&h1;
    *(uint2*)(&dst[(size_t)idx * 4]) = u;
}

// ---------------- enc transpose-convert ----------------
__global__ void __launch_bounds__(256) econv_k(const float* __restrict__ enc) {
    __shared__ float tile[32][33];
    int b = blockIdx.z;
    int k0 = blockIdx.y * 32;
    int t0 = blockIdx.x * 32;
    int tx = threadIdx.x & 31;
    int ty = threadIdx.x >> 5;    // 0..7
    const float* e = enc + (size_t)b * DENC * TT;
#pragma unroll
    for (int r = 0; r < 4; r++) {
        int kk = ty + r * 8;
        tile[kk][tx] = e[(size_t)(k0 + kk) * TT + t0 + tx];
    }
    __syncthreads();
#pragma unroll
    for (int r = 0; r < 4; r++) {
        int tt = ty + r * 8;
        d_ea[(size_t)(b * TT + t0 + tt) * DENC + k0 + tx] =
            __float2half_rn(tile[tx][tt]);
    }
}

// ================= pipelined wmma GEMM common (128x128, BK=64, 2-stage) =========
#define P_LDS 72
#define P_STAGE (128 * P_LDS * 2)       // 18432 bytes
#define P_SMEM (4 * P_STAGE)            // 73728
#define STAG_LD 132

__device__ __forceinline__ void stage_load(uint32_t sbase, int stage,
                                           const __half* ga, size_t lda, int m0,
                                           const __half* gb, size_t ldb, int n0,
                                           int k0, int tid) {
    uint32_t abase = sbase + stage * 2 * P_STAGE;
    uint32_t bbase = abase + P_STAGE;
#pragma unroll
    for (int i = 0; i < 4; i++) {
        int e = i * 256 + tid;            // 0..1023
        int row = e >> 3;                 // 0..127
        int q = (e & 7) << 3;             // halves 0,8,...,56
        cp16(abase + (row * P_LDS + q) * 2, ga + (size_t)(m0 + row) * lda + k0 + q);
        cp16(bbase + (row * P_LDS + q) * 2, gb + (size_t)(n0 + row) * ldb + k0 + q);
    }
}

__device__ __forceinline__ void stage_mma(const __half* smem_gen, int stage,
                                          wmma::fragment<wmma::accumulator, 16, 16, 16, float> (&acc)[4][2],
                                          int wm, int wn) {
    const __half* As = smem_gen + stage * 2 * (128 * P_LDS);
    const __half* Bs = As + 128 * P_LDS;
#pragma unroll
    for (int ks = 0; ks < 4; ks++) {
        wmma::fragment<wmma::matrix_a, 16, 16, 16, __half, wmma::row_major> af[4];
        wmma::fragment<wmma::matrix_b, 16, 16, 16, __half, wmma::col_major> bf[2];
#pragma unroll
        for (int i = 0; i < 4; i++)
            wmma::load_matrix_sync(af[i], &As[(wm * 64 + i * 16) * P_LDS + ks * 16], P_LDS);
#pragma unroll
        for (int j = 0; j < 2; j++)
            wmma::load_matrix_sync(bf[j], &Bs[(wn * 32 + j * 16) * P_LDS + ks * 16], P_LDS);
#pragma unroll
        for (int i = 0; i < 4; i++)
#pragma unroll
            for (int j = 0; j < 2; j++)
                wmma::mma_sync(acc[i][j], af[i], bf[j], acc[i][j]);
    }
}

// ================= fgemm (wmma, pipelined): writes relu(f + encb + g) fp16 ==========
__global__ void __launch_bounds__(256) fgemm_w_k(const float* __restrict__ encb,
                                                 const float* __restrict__ pbias) {
    extern __shared__ char dsm[];
    __half* sh = (__half*)dsm;
    float* stag = (float*)dsm;
    uint32_t sbase = (uint32_t)__cvta_generic_to_shared(dsm);

    int tid = threadIdx.x;
    int wid = tid >> 5;
    int wm = wid >> 2;
    int wn = wid & 3;
    int m0 = blockIdx.x * 128;
    int n0 = blockIdx.y * 128;
    int b = m0 / TT;

    wmma::fragment<wmma::accumulator, 16, 16, 16, float> acc[4][2];
#pragma unroll
    for (int i = 0; i < 4; i++)
#pragma unroll
        for (int j = 0; j < 2; j++) wmma::fill_fragment(acc[i][j], 0.f);

    const int NC = DENC / 64;   // 8
    stage_load(sbase, 0, d_ea, DENC, m0, d_we, DENC, n0, 0, tid);
    cp_commit();
    for (int c = 0; c < NC; c++) {
        cp_wait0();
        __syncthreads();
        if (c + 1 < NC) {
            stage_load(sbase, (c + 1) & 1, d_ea, DENC, m0, d_we, DENC, n0, (c + 1) * 64, tid);
            cp_commit();
        }
        stage_mma(sh, c & 1, acc, wm, wn);
        __syncthreads();
    }

#pragma unroll
    for (int p = 0; p < 2; p++) {
        if (wm == p) {
#pragma unroll
            for (int i = 0; i < 4; i++)
#pragma unroll
                for (int j = 0; j < 2; j++)
                    wmma::store_matrix_sync(&stag[(i * 16) * STAG_LD + wn * 32 + j * 16],
                                            acc[i][j], STAG_LD, wmma::mem_row_major);
        }
        __syncthreads();
        for (int t = tid; t < 64 * 32; t += 256) {
            int rr = t >> 5;
            int c4 = (t & 31) << 2;
            float4 v = *(float4*)(&stag[rr * STAG_LD + c4]);
            float4 eb = *(const float4*)(encb + n0 + c4);
            float4 g0 = *(const float4*)(&d_gvec_p[0][b][n0 + c4]);
            float4 g1 = *(const float4*)(&d_gvec_p[1][b][n0 + c4]);
            float4 g2 = *(const float4*)(&d_gvec_p[2][b][n0 + c4]);
            float4 g3 = *(const float4*)(&d_gvec_p[3][b][n0 + c4]);
            float4 pb = *(const float4*)(pbias + n0 + c4);
            float v0 = fmaxf(v.x + eb.x + g0.x + g1.x + g2.x + g3.x + pb.x, 0.f);
            float v1 = fmaxf(v.y + eb.y + g0.y + g1.y + g2.y + g3.y + pb.y, 0.f);
            float v2 = fmaxf(v.z + eb.z + g0.z + g1.z + g2.z + g3.z + pb.z, 0.f);
            float v3 = fmaxf(v.w + eb.w + g0.w + g1.w + g2.w + g3.w + pb.w, 0.f);
            __half2 h0 = __floats2half2_rn(v0, v1);
            __half2 h1 = __floats2half2_rn(v2, v3);
            uint2 u;
            u.x = *(uint32_t*)&h0;
            u.y = *(uint32_t*)&h1;
            *(uint2*)(&d_fa[(size_t)(m0 + p * 64 + rr) * JJ + n0 + c4]) = u;
        }
        __syncthreads();
    }
}

// ================= out GEMM (wmma, pipelined 128x128, 2-stage) ============
__global__ void __launch_bounds__(256) outgemm_w_k(const float* __restrict__ outb,
                                                   float* __restrict__ out,
                                                   long long out_elems) {
    extern __shared__ char dsm[];
    __half* sh = (__half*)dsm;
    float* stag = (float*)dsm;
    uint32_t sbase = (uint32_t)__cvta_generic_to_shared(dsm);

    int tid = threadIdx.x;
    int wid = tid >> 5;
    int wm = wid >> 2;
    int wn = wid & 3;
    int m0 = blockIdx.x * 128;
    int n0 = blockIdx.y * 128;

    wmma::fragment<wmma::accumulator, 16, 16, 16, float> acc[4][2];
#pragma unroll
    for (int i = 0; i < 4; i++)
#pragma unroll
        for (int j = 0; j < 2; j++) wmma::fill_fragment(acc[i][j], 0.f);

    const int NC = JJ / 64;   // 10
    stage_load(sbase, 0, d_fa, JJ, m0, d_wh, JJ, n0, 0, tid);
    cp_commit();
    for (int c = 0; c < NC; c++) {
        cp_wait0();
        __syncthreads();
        if (c + 1 < NC) {
            stage_load(sbase, (c + 1) & 1, d_fa, JJ, m0, d_wh, JJ, n0, (c + 1) * 64, tid);
            cp_commit();
        }
        stage_mma(sh, c & 1, acc, wm, wn);
        __syncthreads();
    }

#pragma unroll
    for (int p = 0; p < 2; p++) {
        if (wm == p) {
#pragma unroll
            for (int i = 0; i < 4; i++)
#pragma unroll
                for (int j = 0; j < 2; j++)
                    wmma::store_matrix_sync(&stag[(i * 16) * STAG_LD + wn * 32 + j * 16],
                                            acc[i][j], STAG_LD, wmma::mem_row_major);
        }
        __syncthreads();
        for (int t = tid; t < 64 * 32; t += 256) {
            int rr = t >> 5;
            int c4 = (t & 31) << 2;
            float4 v = *(float4*)(&stag[rr * STAG_LD + c4]);
            float4 bias = *(const float4*)(outb + n0 + c4);
            long long idx = (long long)(m0 + p * 64 + rr) * VV + n0 + c4;
            if (idx + 3 < out_elems) {
                float4 o;
                o.x = v.x + bias.x;
                o.y = v.y + bias.y;
                o.z = v.z + bias.z;
                o.w = v.w + bias.w;
                *(float4*)(&out[idx]) = o;
            }
        }
        __syncthreads();
    }
}

// ---------------- tail ----------------
__global__ void tail_k(const int* __restrict__ tlen, float* __restrict__ out,
                       long long out_elems) {
    int i = blockIdx.x * blockDim.x + threadIdx.x;
    long long base = (long long)BB * TT * VV;
    if (i < BB) {
        long long idx = base + i;
        if (idx < out_elems) out[idx] = (float)tlen[i];
    }
    if (i < 2 * BB * HH) {
        float h = (i < BB * HH) ? d_h0[i] : d_h1[i - BB * HH];
        float c = (i < BB * HH) ? d_c0[i] : d_c1[i - BB * HH];
        long long ih = base + BB + i;
        long long ic = base + BB + 2LL * BB * HH + i;
        if (ih < out_elems) out[ih] = h;
        if (ic < out_elems) out[ic] = c;
    }
}

extern "C" void kernel_launch(void* const* d_in, const int* in_sizes, int n_in,
                              void* d_out, int out_size) {
    const float* enc       = (const float*)d_in[0];
    const int* targ        = (const int*)d_in[1];
    const int* tlen        = (const int*)d_in[2];
    const float* st1       = (const float*)d_in[3];
    const float* st2       = (const float*)d_in[4];
    const float* wih0      = (const float*)d_in[5];
    const float* whh0      = (const float*)d_in[6];
    const float* bih0      = (const float*)d_in[7];
    const float* bhh0      = (const float*)d_in[8];
    const float* wih1      = (const float*)d_in[9];
    const float* whh1      = (const float*)d_in[10];
    const float* bih1      = (const float*)d_in[11];
    const float* bhh1      = (const float*)d_in[12];
    const float* embw      = (const float*)d_in[13];
    const float* wenc      = (const float*)d_in[14];
    const float* encb      = (const float*)d_in[15];
    const float* wpred     = (const float*)d_in[16];
    const float* pbias     = (const float*)d_in[17];
    const float* wout      = (const float*)d_in[18];
    const float* outb      = (const float*)d_in[19];
    float* out = (float*)d_out;
    long long out_elems = (long long)out_size;

    cudaFuncSetAttribute(fgemm_w_k, cudaFuncAttributeMaxDynamicSharedMemorySize, P_SMEM);
    cudaFuncSetAttribute(outgemm_w_k, cudaFuncAttributeMaxDynamicSharedMemorySize, P_SMEM);

    wconv2_k<<<(N4_WH + N4_WE + 255) / 256, 256>>>(wout, wenc);
    econv_k<<<dim3(TT / 32, DENC / 32, BB), 256>>>(enc);

    gates2_k<<<dim3(G4 / 128, KSPL), 128>>>(0, targ, embw, st1, wih0, whh0);
    lstm_pw_k<<<(BB * HH + 255) / 256, 256>>>(0, st2, bih0, bhh0);

    gates2_k<<<dim3(G4 / 128, KSPL), 128>>>(1, targ, embw, st1 + (size_t)BB * HH, wih1, whh1);
    lstm_pw_k<<<(BB * HH + 255) / 256, 256>>>(1, st2 + (size_t)BB * HH, bih1, bhh1);

    pred2_k<<<dim3(JJ / 128, PSPL), 128>>>(wpred);

    fgemm_w_k<<<dim3(BB * TT / 128, JJ / 128), 256, P_SMEM>>>(encb, pbias);

    outgemm_w_k<<<dim3(BB * TT / 128, VV / 128), 256, P_SMEM>>>(outb, out, out_elems);

    tail_k<<<(2 * BB * HH + 255) / 256, 256>>>(tlen, out, out_elems);
}